// round 6
// baseline (speedup 1.0000x reference)
#include <cuda_runtime.h>
#include <math.h>

#define BB 16
#define TENC 512
#define DENC 512
#define NMEL 80
#define FRAME 240
#define TSTEPS 200
#define NFRAMES 199
#define PRE 256
#define ARNN 1024
#define ADIM 128
#define LK 31
#define GRID 148
#define NTHR 256

// ---------------- device scratch ----------------
__device__ float g_xraw[NFRAMES * BB * FRAME];
__device__ float g_h1[NFRAMES * BB * PRE];
__device__ float g_preT[TSTEPS * PRE * BB];      // [t][f][b]
__device__ float g_pm[BB * TENC * ADIM];         // [b][t][f]
__device__ float g_procloc[BB * TENC * ADIM];    // [b][t][f]
__device__ float g_haT[ARNN * BB];               // [j][b]
__device__ float g_caT[ARNN * BB];
__device__ float g_hdT[ARNN * BB];
__device__ float g_cdT[ARNN * BB];
__device__ float g_ctxT[DENC * BB];
__device__ float g_w[BB * TENC];
__device__ float g_wcum[BB * TENC];
__device__ float g_pA[8 * 4096 * BB];
__device__ float g_pD[16 * 4096 * BB];
__device__ float g_projC[FRAME * BB];
__device__ unsigned g_cnt;
__device__ volatile unsigned g_sense;

__device__ __forceinline__ float sigf(float x) { return 1.f / (1.f + expf(-x)); }
__device__ __forceinline__ float tanh_fast(float x) {
    float y; asm("tanh.approx.f32 %0, %1;" : "=f"(y) : "f"(x)); return y;
}

// ---------------- software grid barrier (load-polling) ----------------
__device__ __forceinline__ void gsync(unsigned ph) {
    __syncthreads();
    if (threadIdx.x == 0) {
        __threadfence();
        if (atomicAdd(&g_cnt, 1u) == GRID - 1) {
            g_cnt = 0;
            __threadfence();
            g_sense = ph;
        } else {
            while (g_sense != ph) __nanosleep(20);
            __threadfence();
        }
    }
    __syncthreads();
}

// ---------------- init ----------------
__global__ void k_init() {
    int i = blockIdx.x * 256 + threadIdx.x;
    if (i == 0) { g_cnt = 0; g_sense = 0; }
    if (i < ARNN * BB) { g_haT[i] = 0.f; g_caT[i] = 0.f; g_hdT[i] = 0.f; g_cdT[i] = 0.f; }
    if (i < DENC * BB) g_ctxT[i] = 0.f;
    if (i < BB * TENC) { g_w[i] = 0.f; g_wcum[i] = 0.f; }
    if (i < PRE * BB) g_preT[i] = 0.f;
}

// ---------------- gather decoder inputs ----------------
__global__ void k_gather(const float* __restrict__ din) {
    int idx = blockIdx.x * 256 + threadIdx.x;
    if (idx >= NFRAMES * BB * FRAME) return;
    int j = idx % FRAME;
    int m = idx / FRAME;
    int b = m % BB;
    int d = m / BB;
    int flat = d * FRAME + j;
    int col = flat % NMEL;
    int row = flat / NMEL;
    g_xraw[idx] = din[(b * NMEL + col) * 600 + row];
}

// ---------------- prologue tiled SGEMM ----------------
__global__ void k_sgemm(const float* __restrict__ A, const float* __restrict__ Bw,
                        float* __restrict__ C, int M, int N, int K, int relu, int mode) {
    __shared__ float As[16][68];
    __shared__ float Bs[16][68];
    int m0 = blockIdx.x * 64, n0 = blockIdx.y * 64;
    int tx = threadIdx.x;
    int tr = tx >> 4, tc = tx & 15;
    float acc[4][4] = {};
    for (int k0 = 0; k0 < K; k0 += 16) {
        for (int i = tx; i < 1024; i += 256) {
            int mm = i >> 4, kk = i & 15;
            int m = m0 + mm, k = k0 + kk;
            As[kk][mm] = (m < M) ? A[(size_t)m * K + k] : 0.f;
            int n = n0 + mm;
            Bs[kk][mm] = (n < N) ? Bw[(size_t)n * K + k] : 0.f;
        }
        __syncthreads();
#pragma unroll
        for (int kk = 0; kk < 16; kk++) {
            float4 a4 = *(const float4*)&As[kk][tr * 4];
            float4 b4 = *(const float4*)&Bs[kk][tc * 4];
            float a_[4] = {a4.x, a4.y, a4.z, a4.w};
            float b_[4] = {b4.x, b4.y, b4.z, b4.w};
#pragma unroll
            for (int r = 0; r < 4; r++)
#pragma unroll
                for (int c = 0; c < 4; c++) acc[r][c] += a_[r] * b_[c];
        }
        __syncthreads();
    }
    for (int r = 0; r < 4; r++)
        for (int c = 0; c < 4; c++) {
            int m = m0 + tr * 4 + r, n = n0 + tc * 4 + c;
            if (m < M && n < N) {
                float v = acc[r][c];
                if (relu) v = fmaxf(v, 0.f);
                if (mode == 0) C[(size_t)m * N + n] = v;
                else {
                    int d = m >> 4, b = m & 15;
                    C[((d + 1) * PRE + n) * BB + b] = v;
                }
            }
        }
}

// ---------------- cooperative stage: global -> smem ----------------
__device__ __forceinline__ void stage(float* dst, const float* src, int nfloats, int tid) {
    const float4* s4 = (const float4*)src;
    float4* d4 = (float4*)dst;
    int n4 = nfloats >> 2;
    for (int i = tid; i < n4; i += NTHR) d4[i] = __ldcg(s4 + i);
}

// ---------------- gate GEMM segment from smem ----------------
__device__ __forceinline__ void gseg_s(const float* __restrict__ wp, int wstr,
                                       const float* __restrict__ sb, int segstart, int kbeg,
                                       int ks, int ke, int row0, int b0, float acc[4][4]) {
#pragma unroll 2
    for (int k = ks; k < ke; k += 4) {
        const float* ab = sb + (k - kbeg) * BB + b0;
        float4 av0 = *(const float4*)(ab);
        float4 av1 = *(const float4*)(ab + 16);
        float4 av2 = *(const float4*)(ab + 32);
        float4 av3 = *(const float4*)(ab + 48);
        int kl = k - segstart;
#pragma unroll
        for (int r = 0; r < 4; r++) {
            float4 wv = *(const float4*)(wp + (size_t)(row0 + r) * wstr + kl);
            acc[r][0] += wv.x * av0.x + wv.y * av1.x + wv.z * av2.x + wv.w * av3.x;
            acc[r][1] += wv.x * av0.y + wv.y * av1.y + wv.z * av2.y + wv.w * av3.y;
            acc[r][2] += wv.x * av0.z + wv.y * av1.z + wv.z * av2.z + wv.w * av3.z;
            acc[r][3] += wv.x * av0.w + wv.y * av1.w + wv.z * av2.w + wv.w * av3.w;
        }
    }
}

// ---------------- staged gate unit: stage window, compute, write partials ----------------
__device__ __forceinline__ void gate_unit_s(
    float* sbuf,
    const float* w0, int s0, const float* a0, int l0,
    const float* w1, int s1, const float* a1, int l1,
    const float* w2, int s2, const float* a2, int l2,
    float* part, int rowbase, int kbeg, int kend, int tid)
{
    int o0s = kbeg > 0 ? kbeg : 0;
    int o0e = kend < l0 ? kend : l0;
    if (o0e > o0s) stage(sbuf + (o0s - kbeg) * BB, a0 + o0s * BB, (o0e - o0s) * BB, tid);
    int s1s = l0, s1e = l0 + l1;
    int o1s = kbeg > s1s ? kbeg : s1s;
    int o1e = kend < s1e ? kend : s1e;
    if (l1 && o1e > o1s) stage(sbuf + (o1s - kbeg) * BB, a1 + (o1s - s1s) * BB, (o1e - o1s) * BB, tid);
    int s2s = s1e, s2e = s1e + l2;
    int o2s = kbeg > s2s ? kbeg : s2s;
    int o2e = kend < s2e ? kend : s2e;
    if (l2 && o2e > o2s) stage(sbuf + (o2s - kbeg) * BB, a2 + (o2s - s2s) * BB, (o2e - o2s) * BB, tid);
    __syncthreads();
    int row0 = rowbase + (tid >> 2) * 4;
    int b0 = (tid & 3) * 4;
    float acc[4][4] = {};
    if (o0e > o0s) gseg_s(w0, s0, sbuf, 0, kbeg, o0s, o0e, row0, b0, acc);
    if (l1 && o1e > o1s) gseg_s(w1, s1, sbuf, s1s, kbeg, o1s, o1e, row0, b0, acc);
    if (l2 && o2e > o2s) gseg_s(w2, s2, sbuf, s2s, kbeg, o2s, o2e, row0, b0, acc);
#pragma unroll
    for (int r = 0; r < 4; r++)
#pragma unroll
        for (int c = 0; c < 4; c++)
            part[(size_t)(row0 + r) * BB + b0 + c] = acc[r][c];
    __syncthreads();
}

// ---------------- LSTM cell element ----------------
__device__ __forceinline__ void cell(const float* part, int nslots,
                                     const float* bih, const float* bhh,
                                     float* hT, float* cT, int i) {
    int b = i & 15, j = i >> 4;
    float g[4];
#pragma unroll
    for (int gi = 0; gi < 4; gi++) {
        int row = gi * 1024 + j;
        float s = bih[row] + bhh[row];
        for (int sl = 0; sl < nslots; sl++)
            s += __ldcg(&part[((size_t)sl * 4096 + row) * BB + b]);
        g[gi] = s;
    }
    float c = sigf(g[1]) * __ldcg(&cT[i]) + sigf(g[0]) * tanhf(g[2]);
    float h = sigf(g[3]) * tanhf(c);
    cT[i] = c;
    hT[i] = h;
}

// ---------------- location conv + dense unit ----------------
__device__ void loc_unit(int b, int tc, const float* __restrict__ lw,
                         const float* __restrict__ ld_, float* sh, int tid) {
    float* win = sh;
    float* locs = sh + 128;
    int t0 = tc * 32;
    if (tid < 128) {
        int ch = tid >> 6, idx = tid & 63;
        int tt = t0 - 15 + idx;
        bool ok = (tt >= 0 && tt < TENC && idx < 62);
        const float* src = ch ? g_wcum : g_w;
        win[ch * 64 + idx] = ok ? __ldcg(&src[b * TENC + tt]) : 0.f;
    }
    __syncthreads();
    for (int i = tid; i < 1024; i += NTHR) {
        int c = i >> 5, tt = i & 31;
        float acc = 0.f;
#pragma unroll
        for (int ch = 0; ch < 2; ch++)
#pragma unroll
            for (int kk = 0; kk < LK; kk++)
                acc += win[ch * 64 + tt + kk] * lw[c * 62 + ch * LK + kk];
        locs[c * 33 + tt] = acc;
    }
    __syncthreads();
    int f = tid & 127, th = tid >> 7;
    float ldr[32];
#pragma unroll
    for (int c = 0; c < 32; c++) ldr[c] = ld_[f * 32 + c];
    for (int tt = th * 16; tt < th * 16 + 16; tt++) {
        float acc = 0.f;
#pragma unroll
        for (int c = 0; c < 32; c++) acc += locs[c * 33 + tt] * ldr[c];
        g_procloc[((size_t)(b * TENC + t0 + tt)) * ADIM + f] = acc;
    }
    __syncthreads();
}

// ---------------- projection h-part (staged), writes output frame t_prev ----------------
__device__ void proj_h_unit(int t_prev, int rbase, const float* __restrict__ proj_w,
                            const float* __restrict__ proj_b, float* __restrict__ out_mel,
                            float* sbuf, int tid) {
    int r = rbase + (tid >> 4), b = tid & 15;
    float acc = 0.f;
    for (int ch = 0; ch < 4; ch++) {
        stage(sbuf, g_hdT + ch * 256 * BB, 256 * BB, tid);
        __syncthreads();
        if (tid < 128) {
            const float* wr = proj_w + (size_t)r * 1536 + ch * 256;
#pragma unroll 4
            for (int k = 0; k < 256; k += 4) {
                float4 wv = *(const float4*)(wr + k);
                acc += wv.x * sbuf[(k + 0) * BB + b] + wv.y * sbuf[(k + 1) * BB + b] +
                       wv.z * sbuf[(k + 2) * BB + b] + wv.w * sbuf[(k + 3) * BB + b];
            }
        }
        __syncthreads();
    }
    if (tid < 128) {
        acc += __ldcg(&g_projC[r * BB + b]) + proj_b[r];
        int flat = t_prev * FRAME + r;
        int u = flat / NMEL, m = flat % NMEL;
        out_mel[(size_t)b * (NMEL * 600) + m * 600 + u] = acc;
    }
}

// ---------------- the persistent megakernel ----------------
__global__ void __launch_bounds__(NTHR) k_mega(
    const float* __restrict__ memory, const int* __restrict__ mlen,
    const float* __restrict__ aw_ih, const float* __restrict__ aw_hh,
    const float* __restrict__ ab_ih, const float* __restrict__ ab_hh,
    const float* __restrict__ dw_ih, const float* __restrict__ dw_hh,
    const float* __restrict__ db_ih, const float* __restrict__ db_hh,
    const float* __restrict__ Wq, const float* __restrict__ v_att,
    const float* __restrict__ lconv, const float* __restrict__ ldense,
    const float* __restrict__ proj_w, const float* __restrict__ proj_b,
    float* __restrict__ out_mel, float* __restrict__ out_align)
{
    __shared__ float sh[1184];
    __shared__ float sbuf[8192];
    int cta = blockIdx.x, tid = threadIdx.x;
    unsigned ph = 0;

    for (int t = 0; t < TSTEPS; t++) {
        // ===== P1: loc + attn-gate partials =====
        if (cta < 128) {
            int rc = cta >> 3, kc = cta & 7;
            // att_w_ih is (4096, 768): input = [prenet(256); ctx(512)]. Stride 768!
            gate_unit_s(sbuf,
                        aw_ih, 768, g_preT + (size_t)t * PRE * BB, 256,
                        aw_ih + 256, 768, g_ctxT, 512,
                        aw_hh, 1024, g_haT, 1024,
                        g_pA + (size_t)kc * 4096 * BB, rc * 256, kc * 224, kc * 224 + 224, tid);
            loc_unit(cta >> 4, cta & 15, lconv, ldense, sh, tid);
        } else {
            for (int u = 128 + (cta - 128); u < 256; u += 20)
                loc_unit(u >> 4, u & 15, lconv, ldense, sh, tid);
        }
        gsync(++ph);

        // ===== P2: attention LSTM cell || projection(t-1) h-part =====
        if (cta < 64) cell(g_pA, 8, ab_ih, ab_hh, g_haT, g_caT, cta * NTHR + tid);
        else if (t > 0 && cta < 94)
            proj_h_unit(t - 1, (cta - 64) * 8, proj_w, proj_b, out_mel, sbuf, tid);
        gsync(++ph);

        // ===== P3: dec-gate h-parts || attention chain =====
        if (cta < 128) {
            int rc = cta >> 3, kc = cta & 7;
            gate_unit_s(sbuf,
                        dw_ih, 1536, g_haT, 1024,
                        dw_hh, 1024, g_hdT, 1024,
                        (const float*)0, 0, (const float*)0, 0,
                        g_pD + (size_t)kc * 4096 * BB, rc * 256, kc * 256, kc * 256 + 256, tid);
        } else if (cta >= 132) {
            int b = cta - 132;
            // stage h_a column b
            for (int k = tid; k < ARNN; k += NTHR) sbuf[k] = __ldcg(&g_haT[k * BB + b]);
            __syncthreads();
            // q = Wq @ h_a[b]
            if (tid < 128) {
                const float* wr = Wq + (size_t)tid * ARNN;
                float acc = 0.f;
#pragma unroll 4
                for (int k = 0; k < ARNN; k += 4) {
                    float4 wv = *(const float4*)(wr + k);
                    acc += wv.x * sbuf[k] + wv.y * sbuf[k + 1] + wv.z * sbuf[k + 2] + wv.w * sbuf[k + 3];
                }
                sh[tid] = acc;               // qs
                sh[128 + tid] = v_att[tid];  // vs
            }
            __syncthreads();
            // energies + mask
            int L = mlen[b];
            float ev[2];
#pragma unroll
            for (int it = 0; it < 2; it++) {
                int tt = tid + it * 256;
                const float* pl = &g_procloc[((size_t)b * TENC + tt) * ADIM];
                const float* pv = &g_pm[((size_t)b * TENC + tt) * ADIM];
                float acc = 0.f;
#pragma unroll 4
                for (int f = 0; f < ADIM; f += 4) {
                    float4 a = __ldcg((const float4*)(pl + f));
                    float4 p = *(const float4*)(pv + f);
                    acc += sh[128 + f + 0] * tanh_fast(sh[f + 0] + a.x + p.x);
                    acc += sh[128 + f + 1] * tanh_fast(sh[f + 1] + a.y + p.y);
                    acc += sh[128 + f + 2] * tanh_fast(sh[f + 2] + a.z + p.z);
                    acc += sh[128 + f + 3] * tanh_fast(sh[f + 3] + a.w + p.w);
                }
                ev[it] = (tt >= L) ? -1e9f : acc;
            }
            // softmax over 512
            sh[256 + tid] = fmaxf(ev[0], ev[1]);
            __syncthreads();
            for (int s = 128; s > 0; s >>= 1) {
                if (tid < s) sh[256 + tid] = fmaxf(sh[256 + tid], sh[256 + tid + s]);
                __syncthreads();
            }
            float mx = sh[256];
            __syncthreads();
            float ex0 = expf(ev[0] - mx), ex1 = expf(ev[1] - mx);
            sh[256 + tid] = ex0 + ex1;
            __syncthreads();
            for (int s = 128; s > 0; s >>= 1) {
                if (tid < s) sh[256 + tid] += sh[256 + tid + s];
                __syncthreads();
            }
            float inv = 1.f / sh[256];
            {
                int tt = tid;
                float wv = ex0 * inv;
                g_w[b * TENC + tt] = wv;
                g_wcum[b * TENC + tt] = __ldcg(&g_wcum[b * TENC + tt]) + wv;
                out_align[((size_t)b * TSTEPS + t) * TENC + tt] = wv;
                tt = tid + 256;
                wv = ex1 * inv;
                g_w[b * TENC + tt] = wv;
                g_wcum[b * TENC + tt] = __ldcg(&g_wcum[b * TENC + tt]) + wv;
                out_align[((size_t)b * TSTEPS + t) * TENC + tt] = wv;
            }
        }
        gsync(++ph);

        // ===== P4: context = w @ memory =====
        if (cta < 128) {
            int b = cta >> 3, d0 = (cta & 7) * 64;
            for (int i = tid; i < TENC; i += NTHR) sh[i] = __ldcg(&g_w[b * TENC + i]);
            __syncthreads();
            int dd = tid & 63, tq = tid >> 6;
            const float* mb = memory + ((size_t)b * TENC) * DENC + d0 + dd;
            float acc = 0.f;
#pragma unroll 8
            for (int tt = tq * 128; tt < tq * 128 + 128; tt++)
                acc += sh[tt] * mb[(size_t)tt * DENC];
            sh[512 + tid] = acc;
            __syncthreads();
            if (tid < 64) {
                float s = sh[512 + tid] + sh[576 + tid] + sh[640 + tid] + sh[704 + tid];
                g_ctxT[(d0 + tid) * BB + b] = s;
            }
            __syncthreads();
        }
        gsync(++ph);

        // ===== P5: dec-gate ctx-part + proj ctx-part =====
        if (cta < 128) {
            int rc = cta >> 3, kc = cta & 7;
            gate_unit_s(sbuf,
                        dw_ih + 1024, 1536, g_ctxT, 512,
                        (const float*)0, 0, (const float*)0, 0,
                        (const float*)0, 0, (const float*)0, 0,
                        g_pD + (size_t)(8 + kc) * 4096 * BB, rc * 256, kc * 64, kc * 64 + 64, tid);
        } else {
            stage(sbuf, g_ctxT, DENC * BB, tid);
            __syncthreads();
            if (tid < 192) {
                int r = (cta - 128) * 12 + (tid >> 4), b = tid & 15;
                const float* wr = proj_w + (size_t)r * 1536 + 1024;
                float acc = 0.f;
#pragma unroll 4
                for (int k = 0; k < 512; k += 4) {
                    float4 wv = *(const float4*)(wr + k);
                    acc += wv.x * sbuf[(k + 0) * BB + b] + wv.y * sbuf[(k + 1) * BB + b] +
                           wv.z * sbuf[(k + 2) * BB + b] + wv.w * sbuf[(k + 3) * BB + b];
                }
                g_projC[r * BB + b] = acc;
            }
            __syncthreads();
        }
        gsync(++ph);

        // ===== P6: decoder LSTM cell =====
        if (cta < 64) cell(g_pD, 16, db_ih, db_hh, g_hdT, g_cdT, cta * NTHR + tid);
        gsync(++ph);
    }

    // epilogue: final projection for t = TSTEPS-1
    if (cta >= 64 && cta < 94)
        proj_h_unit(TSTEPS - 1, (cta - 64) * 8, proj_w, proj_b, out_mel, sbuf, tid);
}

// ---------------- launch ----------------
extern "C" void kernel_launch(void* const* d_in, const int* in_sizes, int n_in,
                              void* d_out, int out_size) {
    const float* memory = (const float*)d_in[0];
    const float* dec_in = (const float*)d_in[1];
    const int*   mlen   = (const int*)d_in[2];
    const float* pw1    = (const float*)d_in[3];
    const float* pw2    = (const float*)d_in[4];
    const float* aw_ih  = (const float*)d_in[5];
    const float* aw_hh  = (const float*)d_in[6];
    const float* ab_ih  = (const float*)d_in[7];
    const float* ab_hh  = (const float*)d_in[8];
    const float* dw_ih  = (const float*)d_in[9];
    const float* dw_hh  = (const float*)d_in[10];
    const float* db_ih  = (const float*)d_in[11];
    const float* db_hh  = (const float*)d_in[12];
    const float* Wq     = (const float*)d_in[13];
    const float* Wm     = (const float*)d_in[14];
    const float* v_att  = (const float*)d_in[15];
    const float* lconv  = (const float*)d_in[16];
    const float* ldense = (const float*)d_in[17];
    const float* proj_w = (const float*)d_in[18];
    const float* proj_b = (const float*)d_in[19];

    float* out = (float*)d_out;
    float* align_out = out + (size_t)BB * NMEL * 600;

    float *s_xraw, *s_h1, *s_preT, *s_pm;
    cudaGetSymbolAddress((void**)&s_xraw, g_xraw);
    cudaGetSymbolAddress((void**)&s_h1, g_h1);
    cudaGetSymbolAddress((void**)&s_preT, g_preT);
    cudaGetSymbolAddress((void**)&s_pm, g_pm);

    k_init<<<256, 256>>>();
    k_gather<<<(NFRAMES * BB * FRAME + 255) / 256, 256>>>(dec_in);
    k_sgemm<<<dim3(50, 4), 256>>>(s_xraw, pw1, s_h1, NFRAMES * BB, PRE, FRAME, 1, 0);
    k_sgemm<<<dim3(50, 4), 256>>>(s_h1, pw2, s_preT, NFRAMES * BB, PRE, PRE, 1, 1);
    k_sgemm<<<dim3(128, 2), 256>>>(memory, Wm, s_pm, BB * TENC, ADIM, DENC, 0, 0);

    k_mega<<<GRID, NTHR>>>(memory, mlen,
                           aw_ih, aw_hh, ab_ih, ab_hh,
                           dw_ih, dw_hh, db_ih, db_hh,
                           Wq, v_att, lconv, ldense, proj_w, proj_b,
                           out, align_out);
}

// round 7
// speedup vs baseline: 1.2422x; 1.2422x over previous
#include <cuda_runtime.h>
#include <math.h>

#define BB 16
#define TENC 512
#define DENC 512
#define NMEL 80
#define FRAME 240
#define TSTEPS 200
#define NFRAMES 199
#define PRE 256
#define ARNN 1024
#define ADIM 128
#define GRID 148
#define NTHR 256
#define NUNITS 431

__device__ float g_xraw[NFRAMES * BB * FRAME];
__device__ float g_h1[NFRAMES * BB * PRE];
__device__ float g_preT[TSTEPS * PRE * BB];     // [t][f][b]
__device__ float g_pm[BB * TENC * ADIM];
__device__ float g_procloc[BB * TENC * ADIM];
__device__ float g_haT[ARNN * BB];              // [j][b]
__device__ float g_caT[ARNN * BB];
__device__ float g_hdT[ARNN * BB];
__device__ float g_cdT[ARNN * BB];
__device__ float g_ctx[2 * DENC * BB];          // [parity][d][b]
__device__ float g_w[BB * TENC];
__device__ float g_wcum[BB * TENC];
__device__ float g_pA[8 * BB * 4096];           // [slot][b][row]
__device__ float g_pD[10 * BB * 4096];
__device__ int   g_wflag[BB * 32];
__device__ unsigned g_qcnt[TSTEPS];
__device__ __align__(128) unsigned g_barA[32];
__device__ __align__(128) unsigned g_barB[32];

__device__ __forceinline__ float sigf(float x) { return 1.f / (1.f + expf(-x)); }
__device__ __forceinline__ float tanh_fast(float x) {
    float y; asm("tanh.approx.f32 %0, %1;" : "=f"(y) : "f"(x)); return y;
}

__device__ __forceinline__ void gsync(unsigned ph) {
    __threadfence();
    __syncthreads();
    if (threadIdx.x == 0) {
        if (atomicAdd(&g_barA[0], 1u) == GRID - 1) {
            g_barA[0] = 0;
            __threadfence();
            *(volatile unsigned*)&g_barB[0] = ph;
        } else {
            while (*(volatile unsigned*)&g_barB[0] != ph) __nanosleep(32);
            __threadfence();
        }
    }
    __syncthreads();
}

__global__ void k_init() {
    int i = blockIdx.x * 256 + threadIdx.x;
    int st = gridDim.x * 256;
    if (i == 0) { g_barA[0] = 0; g_barB[0] = 0; }
    if (i < TSTEPS) g_qcnt[i] = 0;
    for (int k = i; k < ARNN * BB; k += st) { g_haT[k]=0.f; g_caT[k]=0.f; g_hdT[k]=0.f; g_cdT[k]=0.f; }
    for (int k = i; k < 2 * DENC * BB; k += st) g_ctx[k] = 0.f;
    for (int k = i; k < BB * TENC; k += st) { g_w[k] = 0.f; g_wcum[k] = 0.f; }
    for (int k = i; k < PRE * BB; k += st) g_preT[k] = 0.f;
    for (int k = i; k < BB * 32; k += st) g_wflag[k] = 0;
    for (int k = i; k < 8 * BB * 4096; k += st) g_pA[k] = 0.f;
    for (int k = i; k < BB * TENC * ADIM; k += st) g_procloc[k] = 0.f;
}

__global__ void k_gather(const float* __restrict__ din) {
    int idx = blockIdx.x * 256 + threadIdx.x;
    if (idx >= NFRAMES * BB * FRAME) return;
    int j = idx % FRAME, m = idx / FRAME;
    int b = m % BB, d = m / BB;
    int flat = d * FRAME + j;
    g_xraw[idx] = din[(b * NMEL + flat % NMEL) * 600 + flat / NMEL];
}

__global__ void k_sgemm(const float* __restrict__ A, const float* __restrict__ Bw,
                        float* __restrict__ C, int M, int N, int K, int relu, int mode) {
    __shared__ float As[16][68];
    __shared__ float Bs[16][68];
    int m0 = blockIdx.x * 64, n0 = blockIdx.y * 64;
    int tx = threadIdx.x, tr = tx >> 4, tc = tx & 15;
    float acc[4][4] = {};
    for (int k0 = 0; k0 < K; k0 += 16) {
        for (int i = tx; i < 1024; i += 256) {
            int mm = i >> 4, kk = i & 15;
            int m = m0 + mm, k = k0 + kk;
            As[kk][mm] = (m < M) ? A[(size_t)m * K + k] : 0.f;
            int n = n0 + mm;
            Bs[kk][mm] = (n < N) ? Bw[(size_t)n * K + k] : 0.f;
        }
        __syncthreads();
#pragma unroll
        for (int kk = 0; kk < 16; kk++) {
            float4 a4 = *(const float4*)&As[kk][tr * 4];
            float4 b4 = *(const float4*)&Bs[kk][tc * 4];
            float a_[4] = {a4.x, a4.y, a4.z, a4.w};
            float b_[4] = {b4.x, b4.y, b4.z, b4.w};
#pragma unroll
            for (int r = 0; r < 4; r++)
#pragma unroll
                for (int c = 0; c < 4; c++) acc[r][c] += a_[r] * b_[c];
        }
        __syncthreads();
    }
    for (int r = 0; r < 4; r++)
        for (int c = 0; c < 4; c++) {
            int m = m0 + tr * 4 + r, n = n0 + tc * 4 + c;
            if (m < M && n < N) {
                float v = acc[r][c];
                if (relu) v = fmaxf(v, 0.f);
                if (mode == 0) C[(size_t)m * N + n] = v;
                else C[(((m >> 4) + 1) * PRE + n) * BB + (m & 15)] = v;
            }
        }
}

__device__ __forceinline__ void stage(float* dst, const float* src, int nfloats, int tid) {
    const float4* s4 = (const float4*)src;
    float4* d4 = (float4*)dst;
    int n4 = nfloats >> 2;
    for (int i = tid; i < n4; i += NTHR) d4[i] = __ldcg(s4 + i);
}

__device__ __forceinline__ void gseg(const float* __restrict__ wp, int wstr,
                                     const float* __restrict__ sb, int segstart, int kbeg,
                                     int ks, int ke, int row0, int b0, float acc[4][4]) {
#pragma unroll 2
    for (int k = ks; k < ke; k += 4) {
        const float* ab = sb + (k - kbeg) * BB + b0;
        float4 av0 = *(const float4*)(ab);
        float4 av1 = *(const float4*)(ab + 16);
        float4 av2 = *(const float4*)(ab + 32);
        float4 av3 = *(const float4*)(ab + 48);
        int kl = k - segstart;
#pragma unroll
        for (int r = 0; r < 4; r++) {
            float4 wv = *(const float4*)(wp + (size_t)(row0 + r) * wstr + kl);
            acc[r][0] += wv.x * av0.x + wv.y * av1.x + wv.z * av2.x + wv.w * av3.x;
            acc[r][1] += wv.x * av0.y + wv.y * av1.y + wv.z * av2.y + wv.w * av3.y;
            acc[r][2] += wv.x * av0.z + wv.y * av1.z + wv.z * av2.z + wv.w * av3.z;
            acc[r][3] += wv.x * av0.w + wv.y * av1.w + wv.z * av2.w + wv.w * av3.w;
        }
    }
}

// one gate unit: 256 rows x one K chunk; partial layout [slot][b][row]
__device__ void gate_unit(float* sbuf,
    const float* w0, int s0, const float* a0, int l0,
    const float* w1, int s1, const float* a1, int l1,
    const float* w2, int s2, const float* a2, int l2,
    float* part, int slot, int rowbase, int kbeg, int kend, int tid)
{
    int o0s = max(kbeg, 0), o0e = min(kend, l0);
    if (o0e > o0s) stage(sbuf + (o0s - kbeg) * BB, a0 + o0s * BB, (o0e - o0s) * BB, tid);
    int s1s = l0, s1e = l0 + l1;
    int o1s = max(kbeg, s1s), o1e = min(kend, s1e);
    if (l1 && o1e > o1s) stage(sbuf + (o1s - kbeg) * BB, a1 + (o1s - s1s) * BB, (o1e - o1s) * BB, tid);
    int s2s = s1e, s2e = s1e + l2;
    int o2s = max(kbeg, s2s), o2e = min(kend, s2e);
    if (l2 && o2e > o2s) stage(sbuf + (o2s - kbeg) * BB, a2 + (o2s - s2s) * BB, (o2e - o2s) * BB, tid);
    __syncthreads();
    int row0 = rowbase + (tid >> 2) * 4;
    int b0 = (tid & 3) * 4;
    float acc[4][4] = {};
    if (o0e > o0s) gseg(w0, s0, sbuf, 0, kbeg, o0s, o0e, row0, b0, acc);
    if (l1 && o1e > o1s) gseg(w1, s1, sbuf, s1s, kbeg, o1s, o1e, row0, b0, acc);
    if (l2 && o2e > o2s) gseg(w2, s2, sbuf, s2s, kbeg, o2s, o2e, row0, b0, acc);
#pragma unroll
    for (int c = 0; c < 4; c++) {
        float4 v = make_float4(acc[0][c], acc[1][c], acc[2][c], acc[3][c]);
        *(float4*)&part[(size_t)((slot * BB + b0 + c) << 12) + row0] = v;
    }
    __syncthreads();
}

// loc conv+dense for one (b, 64-wide t chunk)
__device__ void loc64(int b, int e, const float* __restrict__ lw,
                      const float* __restrict__ ld_, float* sbuf, int tid) {
    float* win = sbuf;           // 2 x 96
    float* locs = sbuf + 192;    // 32 x 64
    int t0 = e * 64;
    if (tid < 192) {
        int ch = tid / 96, idx = tid % 96;
        int tt = t0 - 15 + idx;
        bool ok = (idx < 94) && (tt >= 0) && (tt < TENC);
        const float* src = ch ? g_wcum : g_w;
        win[ch * 96 + idx] = ok ? __ldcg(&src[b * TENC + tt]) : 0.f;
    }
    __syncthreads();
    for (int i = tid; i < 2048; i += NTHR) {
        int c = i >> 6, tt = i & 63;
        float acc = 0.f;
#pragma unroll
        for (int ch = 0; ch < 2; ch++)
#pragma unroll
            for (int kk = 0; kk < 31; kk++)
                acc += win[ch * 96 + tt + kk] * lw[c * 62 + ch * 31 + kk];
        locs[c * 64 + tt] = acc;
    }
    __syncthreads();
    int f = tid & 127, tg = tid >> 7;
    float ldr[32];
#pragma unroll
    for (int c = 0; c < 32; c++) ldr[c] = ld_[f * 32 + c];
    for (int tt = tg * 32; tt < tg * 32 + 32; tt++) {
        float acc = 0.f;
#pragma unroll
        for (int c = 0; c < 32; c++) acc += locs[c * 64 + tt] * ldr[c];
        g_procloc[((size_t)(b * TENC + t0 + tt)) * ADIM + f] = acc;
    }
    __syncthreads();
}

// full-K projection for 16 rows; writes output frame t-1
__device__ void proj_unit(int t, int v, const float* __restrict__ pw,
                          const float* __restrict__ pb, float* __restrict__ out_mel, int tid) {
    int r = v * 16 + (tid >> 4), b = tid & 15;
    const float* wr = pw + (size_t)r * 1536;
    const float* hd = g_hdT + b;
    const float* cx = g_ctx + ((t - 1) & 1) * DENC * BB + b;
    float a0 = 0.f, a1 = 0.f, a2 = 0.f, a3 = 0.f;
    for (int k = 0; k < 1024; k += 4) {
        a0 += wr[k + 0] * __ldcg(&hd[(k + 0) * BB]);
        a1 += wr[k + 1] * __ldcg(&hd[(k + 1) * BB]);
        a2 += wr[k + 2] * __ldcg(&hd[(k + 2) * BB]);
        a3 += wr[k + 3] * __ldcg(&hd[(k + 3) * BB]);
    }
    for (int k = 0; k < 512; k += 4) {
        a0 += wr[1024 + k + 0] * __ldcg(&cx[(k + 0) * BB]);
        a1 += wr[1024 + k + 1] * __ldcg(&cx[(k + 1) * BB]);
        a2 += wr[1024 + k + 2] * __ldcg(&cx[(k + 2) * BB]);
        a3 += wr[1024 + k + 3] * __ldcg(&cx[(k + 3) * BB]);
    }
    float acc = a0 + a1 + a2 + a3 + pb[r];
    int flat = (t - 1) * FRAME + r;
    out_mel[(size_t)b * (NMEL * 600) + (flat % NMEL) * 600 + flat / NMEL] = acc;
}

__global__ void __launch_bounds__(NTHR) k_mega(
    const float* __restrict__ memory, const int* __restrict__ mlen,
    const float* __restrict__ aw_ih, const float* __restrict__ aw_hh,
    const float* __restrict__ ab_ih, const float* __restrict__ ab_hh,
    const float* __restrict__ dw_ih, const float* __restrict__ dw_hh,
    const float* __restrict__ db_ih, const float* __restrict__ db_hh,
    const float* __restrict__ Wq, const float* __restrict__ v_att,
    const float* __restrict__ lconv, const float* __restrict__ ldense,
    const float* __restrict__ proj_w, const float* __restrict__ proj_b,
    float* __restrict__ out_mel, float* __restrict__ out_align)
{
    __shared__ float sh[1792];
    __shared__ float sbuf[4096];
    __shared__ int sh_u;
    int cta = blockIdx.x, tid = threadIdx.x;
    unsigned ph = 0;

    for (int t = 0; t <= TSTEPS; t++) {
        // =========== Phase A ===========
        if (cta < 16 && t < TSTEPS) {
            int b = cta;
            float* s_ha = sh;            // [1024]
            // attention LSTM cell for this b (reduce 8 partial slots)
            for (int j = tid; j < ARNN; j += NTHR) {
                float g[4];
#pragma unroll
                for (int gi = 0; gi < 4; gi++) {
                    int row = gi * 1024 + j;
                    float s = ab_ih[row] + ab_hh[row];
#pragma unroll
                    for (int sl = 0; sl < 8; sl++)
                        s += __ldcg(&g_pA[(size_t)((sl * BB + b) << 12) + row]);
                    g[gi] = s;
                }
                float c = sigf(g[1]) * __ldcg(&g_caT[j * BB + b]) + sigf(g[0]) * tanhf(g[2]);
                float h = sigf(g[3]) * tanhf(c);
                g_caT[j * BB + b] = c;
                g_haT[j * BB + b] = h;
                s_ha[j] = h;
            }
            __syncthreads();
            // q = Wq @ h_a[b], K split in 2 halves
            {
                int f = tid & 127, hf = tid >> 7;
                const float* wr = Wq + (size_t)f * ARNN + hf * 512;
                const float* ha = s_ha + hf * 512;
                float acc = 0.f;
#pragma unroll 4
                for (int k = 0; k < 512; k += 4) {
                    float4 wv = *(const float4*)(wr + k);
                    acc += wv.x * ha[k] + wv.y * ha[k + 1] + wv.z * ha[k + 2] + wv.w * ha[k + 3];
                }
                sh[1024 + tid] = acc;
            }
            __syncthreads();
            if (tid < 128) {
                sh[1280 + tid] = sh[1024 + tid] + sh[1152 + tid];  // qv
                sh[1408 + tid] = v_att[tid];                       // vs
            }
            __syncthreads();
            // energies + mask
            int L = mlen[b];
            float ev[2];
#pragma unroll
            for (int it = 0; it < 2; it++) {
                int tt = tid + it * 256;
                const float* pl = &g_procloc[((size_t)b * TENC + tt) * ADIM];
                const float* pv = &g_pm[((size_t)b * TENC + tt) * ADIM];
                float acc = 0.f;
#pragma unroll 4
                for (int f = 0; f < ADIM; f += 4) {
                    float4 a = __ldcg((const float4*)(pl + f));
                    float4 p = *(const float4*)(pv + f);
                    acc += sh[1408 + f + 0] * tanh_fast(sh[1280 + f + 0] + a.x + p.x);
                    acc += sh[1408 + f + 1] * tanh_fast(sh[1280 + f + 1] + a.y + p.y);
                    acc += sh[1408 + f + 2] * tanh_fast(sh[1280 + f + 2] + a.z + p.z);
                    acc += sh[1408 + f + 3] * tanh_fast(sh[1280 + f + 3] + a.w + p.w);
                }
                ev[it] = (tt >= L) ? -1e9f : acc;
            }
            float* red = sh + 1536;
            red[tid] = fmaxf(ev[0], ev[1]);
            __syncthreads();
            for (int s = 128; s > 0; s >>= 1) {
                if (tid < s) red[tid] = fmaxf(red[tid], red[tid + s]);
                __syncthreads();
            }
            float mx = red[0];
            __syncthreads();
            float ex0 = expf(ev[0] - mx), ex1 = expf(ev[1] - mx);
            red[tid] = ex0 + ex1;
            __syncthreads();
            for (int s = 128; s > 0; s >>= 1) {
                if (tid < s) red[tid] += red[tid + s];
                __syncthreads();
            }
            float inv = 1.f / red[0];
            {
                float wv = ex0 * inv;
                g_w[b * TENC + tid] = wv;
                g_wcum[b * TENC + tid] = __ldcg(&g_wcum[b * TENC + tid]) + wv;
                out_align[((size_t)b * TSTEPS + t) * TENC + tid] = wv;
                wv = ex1 * inv;
                g_w[b * TENC + tid + 256] = wv;
                g_wcum[b * TENC + tid + 256] = __ldcg(&g_wcum[b * TENC + tid + 256]) + wv;
                out_align[((size_t)b * TSTEPS + t) * TENC + tid + 256] = wv;
            }
            __syncthreads();
            __threadfence();
            if (tid == 0) *(volatile int*)&g_wflag[b * 32] = t + 1;
        } else if (cta >= 16 && cta < 80 && t < TSTEPS) {
            // ctx helpers: 4 CTAs per b, 128-d slice each
            int v = cta - 16, b = v >> 2, d0 = (v & 3) * 128;
            if (tid == 0) {
                while (*(volatile int*)&g_wflag[b * 32] != t + 1) __nanosleep(32);
            }
            __syncthreads();
            for (int i = tid; i < TENC; i += NTHR) sh[i] = __ldcg(&g_w[b * TENC + i]);
            __syncthreads();
            int dd = tid & 127, hf = tid >> 7;
            const float* mb = memory + ((size_t)b * TENC + hf * 256) * DENC + d0 + dd;
            float acc = 0.f;
#pragma unroll 8
            for (int tt = 0; tt < 256; tt++)
                acc += sh[hf * 256 + tt] * mb[(size_t)tt * DENC];
            sh[512 + tid] = acc;
            __syncthreads();
            if (tid < 128)
                g_ctx[(t & 1) * DENC * BB + (d0 + tid) * BB + b] = sh[512 + tid] + sh[640 + tid];
        } else if (cta >= 80 && cta < 144 && t > 0) {
            // decoder LSTM cell for step t-1 (reduce 10 partial slots)
            int v = cta - 80, b = v >> 2, j = (v & 3) * 256 + tid;
            float g[4];
#pragma unroll
            for (int gi = 0; gi < 4; gi++) {
                int row = gi * 1024 + j;
                float s = db_ih[row] + db_hh[row];
#pragma unroll
                for (int sl = 0; sl < 10; sl++)
                    s += __ldcg(&g_pD[(size_t)((sl * BB + b) << 12) + row]);
                g[gi] = s;
            }
            float c = sigf(g[1]) * __ldcg(&g_cdT[j * BB + b]) + sigf(g[0]) * tanhf(g[2]);
            float h = sigf(g[3]) * tanhf(c);
            g_cdT[j * BB + b] = c;
            g_hdT[j * BB + b] = h;
        }
        gsync(++ph);
        if (t == TSTEPS) break;

        // =========== Phase B: dynamic work queue ===========
        const float* ctx_t = g_ctx + (t & 1) * DENC * BB;
        for (;;) {
            if (tid == 0) sh_u = (int)atomicAdd(&g_qcnt[t], 1u);
            __syncthreads();
            int u = sh_u;
            __syncthreads();
            if (u >= NUNITS) break;
            if (u < 128) {
                if (t < TSTEPS - 1) {
                    int rc = u >> 3, kc = u & 7;
                    gate_unit(sbuf,
                              aw_ih, 768, g_preT + (size_t)(t + 1) * PRE * BB, 256,
                              aw_ih + 256, 768, ctx_t, 512,
                              aw_hh, 1024, g_haT, 1024,
                              g_pA, kc, rc * 256, kc * 224, kc * 224 + 224, tid);
                }
            } else if (u < 288) {
                int v = u - 128, rc = v / 10, kc = v % 10;
                gate_unit(sbuf,
                          dw_ih, 1536, g_haT, 1024,
                          dw_ih + 1024, 1536, ctx_t, 512,
                          dw_hh, 1024, g_hdT, 1024,
                          g_pD, kc, rc * 256, kc * 256, kc * 256 + 256, tid);
            } else if (u < 416) {
                if (t < TSTEPS - 1) {
                    int v = u - 288;
                    loc64(v >> 3, v & 7, lconv, ldense, sbuf, tid);
                }
            } else {
                if (t > 0) proj_unit(t, u - 416, proj_w, proj_b, out_mel, tid);
            }
        }
        gsync(++ph);
    }

    // epilogue: projection for final frame t=199 (h_d(199) computed in last Phase A)
    if (cta < 15) proj_unit(TSTEPS, cta, proj_w, proj_b, out_mel, tid);
}

extern "C" void kernel_launch(void* const* d_in, const int* in_sizes, int n_in,
                              void* d_out, int out_size) {
    const float* memory = (const float*)d_in[0];
    const float* dec_in = (const float*)d_in[1];
    const int*   mlen   = (const int*)d_in[2];
    const float* pw1    = (const float*)d_in[3];
    const float* pw2    = (const float*)d_in[4];
    const float* aw_ih  = (const float*)d_in[5];
    const float* aw_hh  = (const float*)d_in[6];
    const float* ab_ih  = (const float*)d_in[7];
    const float* ab_hh  = (const float*)d_in[8];
    const float* dw_ih  = (const float*)d_in[9];
    const float* dw_hh  = (const float*)d_in[10];
    const float* db_ih  = (const float*)d_in[11];
    const float* db_hh  = (const float*)d_in[12];
    const float* Wq     = (const float*)d_in[13];
    const float* Wm     = (const float*)d_in[14];
    const float* v_att  = (const float*)d_in[15];
    const float* lconv  = (const float*)d_in[16];
    const float* ldense = (const float*)d_in[17];
    const float* proj_w = (const float*)d_in[18];
    const float* proj_b = (const float*)d_in[19];

    float* out = (float*)d_out;
    float* align_out = out + (size_t)BB * NMEL * 600;

    float *s_xraw, *s_h1, *s_preT, *s_pm;
    cudaGetSymbolAddress((void**)&s_xraw, g_xraw);
    cudaGetSymbolAddress((void**)&s_h1, g_h1);
    cudaGetSymbolAddress((void**)&s_preT, g_preT);
    cudaGetSymbolAddress((void**)&s_pm, g_pm);

    k_init<<<256, 256>>>();
    k_gather<<<(NFRAMES * BB * FRAME + 255) / 256, 256>>>(dec_in);
    k_sgemm<<<dim3(50, 4), 256>>>(s_xraw, pw1, s_h1, NFRAMES * BB, PRE, FRAME, 1, 0);
    k_sgemm<<<dim3(50, 4), 256>>>(s_h1, pw2, s_preT, NFRAMES * BB, PRE, PRE, 1, 1);
    k_sgemm<<<dim3(128, 2), 256>>>(memory, Wm, s_pm, BB * TENC, ADIM, DENC, 0, 0);

    k_mega<<<GRID, NTHR>>>(memory, mlen,
                           aw_ih, aw_hh, ab_ih, ab_hh,
                           dw_ih, dw_hh, db_ih, db_hh,
                           Wq, v_att, lconv, ldense, proj_w, proj_b,
                           out, align_out);
}

// round 8
// speedup vs baseline: 1.3698x; 1.1027x over previous
#include <cuda_runtime.h>
#include <math.h>

#define BB 16
#define TENC 512
#define DENC 512
#define NMEL 80
#define FRAME 240
#define TSTEPS 200
#define NFRAMES 199
#define PRE 256
#define ARNN 1024
#define ADIM 128
#define GRID 148
#define NTHR 256
#define NUNITS 431
#define WB_STRIDE 36
#define SMEM_FLOATS (4096 + 2 * 256 * WB_STRIDE)   // act + 2 weight buffers

__device__ float g_xraw[NFRAMES * BB * FRAME];
__device__ float g_h1[NFRAMES * BB * PRE];
__device__ float g_preT[TSTEPS * PRE * BB];     // [t][f][b]
__device__ float g_pm[BB * TENC * ADIM];
__device__ float g_procloc[BB * TENC * ADIM];
__device__ float g_haT[ARNN * BB];              // [j][b]
__device__ float g_caT[ARNN * BB];
__device__ float g_hdT[ARNN * BB];
__device__ float g_cdT[ARNN * BB];
__device__ float g_ctx[2 * DENC * BB];          // [parity][d][b]
__device__ float g_w[BB * TENC];
__device__ float g_wcum[BB * TENC];
__device__ float g_pA[8 * BB * 4096];           // [slot][b][row]
__device__ float g_pD[10 * BB * 4096];
__device__ int   g_wflag[BB * 32];
__device__ unsigned g_qcnt[TSTEPS];
__device__ __align__(128) unsigned g_barA[32];
__device__ __align__(128) unsigned g_barB[32];

__device__ __forceinline__ float sigf(float x) { return 1.f / (1.f + expf(-x)); }
__device__ __forceinline__ float tanh_fast(float x) {
    float y; asm("tanh.approx.f32 %0, %1;" : "=f"(y) : "f"(x)); return y;
}

// ---- cp.async helpers ----
__device__ __forceinline__ void cp16(float* s, const float* g) {
    unsigned ss = (unsigned)__cvta_generic_to_shared(s);
    asm volatile("cp.async.ca.shared.global [%0], [%1], 16;" :: "r"(ss), "l"(g));
}
__device__ __forceinline__ void cp_commit() { asm volatile("cp.async.commit_group;"); }
__device__ __forceinline__ void cp_wait0() { asm volatile("cp.async.wait_group 0;"); }
__device__ __forceinline__ void cp_wait1() { asm volatile("cp.async.wait_group 1;"); }

__device__ __forceinline__ void gsync(unsigned ph) {
    __threadfence();
    __syncthreads();
    if (threadIdx.x == 0) {
        if (atomicAdd(&g_barA[0], 1u) == GRID - 1) {
            g_barA[0] = 0;
            __threadfence();
            *(volatile unsigned*)&g_barB[0] = ph;
        } else {
            while (*(volatile unsigned*)&g_barB[0] != ph) __nanosleep(32);
            __threadfence();
        }
    }
    __syncthreads();
}

__global__ void k_init() {
    int i = blockIdx.x * 256 + threadIdx.x;
    int st = gridDim.x * 256;
    if (i == 0) { g_barA[0] = 0; g_barB[0] = 0; }
    if (i < TSTEPS) g_qcnt[i] = 0;
    for (int k = i; k < ARNN * BB; k += st) { g_haT[k]=0.f; g_caT[k]=0.f; g_hdT[k]=0.f; g_cdT[k]=0.f; }
    for (int k = i; k < 2 * DENC * BB; k += st) g_ctx[k] = 0.f;
    for (int k = i; k < BB * TENC; k += st) { g_w[k] = 0.f; g_wcum[k] = 0.f; }
    for (int k = i; k < PRE * BB; k += st) g_preT[k] = 0.f;
    for (int k = i; k < BB * 32; k += st) g_wflag[k] = 0;
    for (int k = i; k < 8 * BB * 4096; k += st) g_pA[k] = 0.f;
    for (int k = i; k < BB * TENC * ADIM; k += st) g_procloc[k] = 0.f;
}

__global__ void k_gather(const float* __restrict__ din) {
    int idx = blockIdx.x * 256 + threadIdx.x;
    if (idx >= NFRAMES * BB * FRAME) return;
    int j = idx % FRAME, m = idx / FRAME;
    int b = m % BB, d = m / BB;
    int flat = d * FRAME + j;
    g_xraw[idx] = din[(b * NMEL + flat % NMEL) * 600 + flat / NMEL];
}

__global__ void k_sgemm(const float* __restrict__ A, const float* __restrict__ Bw,
                        float* __restrict__ C, int M, int N, int K, int relu, int mode) {
    __shared__ float As[16][68];
    __shared__ float Bs[16][68];
    int m0 = blockIdx.x * 64, n0 = blockIdx.y * 64;
    int tx = threadIdx.x, tr = tx >> 4, tc = tx & 15;
    float acc[4][4] = {};
    for (int k0 = 0; k0 < K; k0 += 16) {
        for (int i = tx; i < 1024; i += 256) {
            int mm = i >> 4, kk = i & 15;
            int m = m0 + mm, k = k0 + kk;
            As[kk][mm] = (m < M) ? A[(size_t)m * K + k] : 0.f;
            int n = n0 + mm;
            Bs[kk][mm] = (n < N) ? Bw[(size_t)n * K + k] : 0.f;
        }
        __syncthreads();
#pragma unroll
        for (int kk = 0; kk < 16; kk++) {
            float4 a4 = *(const float4*)&As[kk][tr * 4];
            float4 b4 = *(const float4*)&Bs[kk][tc * 4];
            float a_[4] = {a4.x, a4.y, a4.z, a4.w};
            float b_[4] = {b4.x, b4.y, b4.z, b4.w};
#pragma unroll
            for (int r = 0; r < 4; r++)
#pragma unroll
                for (int c = 0; c < 4; c++) acc[r][c] += a_[r] * b_[c];
        }
        __syncthreads();
    }
    for (int r = 0; r < 4; r++)
        for (int c = 0; c < 4; c++) {
            int m = m0 + tr * 4 + r, n = n0 + tc * 4 + c;
            if (m < M && n < N) {
                float v = acc[r][c];
                if (relu) v = fmaxf(v, 0.f);
                if (mode == 0) C[(size_t)m * N + n] = v;
                else C[(((m >> 4) + 1) * PRE + n) * BB + (m & 15)] = v;
            }
        }
}

__device__ __forceinline__ void stage(float* dst, const float* src, int nfloats, int tid) {
    const float4* s4 = (const float4*)src;
    float4* d4 = (float4*)dst;
    int n4 = nfloats >> 2;
    for (int i = tid; i < n4; i += NTHR) d4[i] = __ldcg(s4 + i);
}

// ---- cp.async-pipelined gate unit: 256 rows x W k-cols ----
// weights: global k < lenA -> wA + row*strA + k; else wB + row*strB + (k-lenA)
// (lenA, kbeg, W all multiples of 32 so each 32-chunk is on one side)
__device__ void gate_unit2(float* act, float* wbufs,
    const float* wA, int strA, int lenA, const float* wB, int strB,
    const float* a0, int l0, const float* a1, int l1, const float* a2, int l2,
    float* part, int slot, int rowbase, int kbeg, int W, int tid)
{
    int kend = kbeg + W;
    // stage activations [kbeg, kend) -> act[(k-kbeg)*16 + b]
    {
        int o0s = max(kbeg, 0), o0e = min(kend, l0);
        if (o0e > o0s) stage(act + (o0s - kbeg) * BB, a0 + o0s * BB, (o0e - o0s) * BB, tid);
        int s1s = l0, s1e = l0 + l1;
        int o1s = max(kbeg, s1s), o1e = min(kend, s1e);
        if (l1 && o1e > o1s) stage(act + (o1s - kbeg) * BB, a1 + (o1s - s1s) * BB, (o1e - o1s) * BB, tid);
        int s2s = s1e, s2e = s1e + l2;
        int o2s = max(kbeg, s2s), o2e = min(kend, s2e);
        if (l2 && o2e > o2s) stage(act + (o2s - kbeg) * BB, a2 + (o2s - s2s) * BB, (o2e - o2s) * BB, tid);
    }
    int nch = W >> 5;
    int lrow = tid >> 3, lkq = (tid & 7) * 4;
    // prefetch chunk 0
    {
        int kg = kbeg;
        const float* ws; int wst; int ko;
        if (kg < lenA) { ws = wA; wst = strA; ko = kg; } else { ws = wB; wst = strB; ko = kg - lenA; }
#pragma unroll
        for (int i = 0; i < 8; i++) {
            int row = lrow + i * 32;
            cp16(wbufs + row * WB_STRIDE + lkq, ws + (size_t)(rowbase + row) * wst + ko + lkq);
        }
        cp_commit();
    }
    int rg = tid >> 2, b4 = (tid & 3) * 4;
    float acc[4][4] = {};
    for (int c = 0; c < nch; c++) {
        if (c + 1 < nch) {
            int kg = kbeg + (c + 1) * 32;
            const float* ws; int wst; int ko;
            if (kg < lenA) { ws = wA; wst = strA; ko = kg; } else { ws = wB; wst = strB; ko = kg - lenA; }
            float* dst = wbufs + ((c + 1) & 1) * (256 * WB_STRIDE);
#pragma unroll
            for (int i = 0; i < 8; i++) {
                int row = lrow + i * 32;
                cp16(dst + row * WB_STRIDE + lkq, ws + (size_t)(rowbase + row) * wst + ko + lkq);
            }
            cp_commit();
            cp_wait1();
        } else {
            cp_wait0();
        }
        __syncthreads();
        const float* wb = wbufs + (c & 1) * (256 * WB_STRIDE);
        const float* ac = act + c * 32 * BB;
#pragma unroll
        for (int l = 0; l < 32; l += 4) {
            float4 av0 = *(const float4*)&ac[(l + 0) * BB + b4];
            float4 av1 = *(const float4*)&ac[(l + 1) * BB + b4];
            float4 av2 = *(const float4*)&ac[(l + 2) * BB + b4];
            float4 av3 = *(const float4*)&ac[(l + 3) * BB + b4];
#pragma unroll
            for (int m = 0; m < 4; m++) {
                float4 w = *(const float4*)&wb[(rg + (m << 6)) * WB_STRIDE + l];
                acc[m][0] += w.x * av0.x + w.y * av1.x + w.z * av2.x + w.w * av3.x;
                acc[m][1] += w.x * av0.y + w.y * av1.y + w.z * av2.y + w.w * av3.y;
                acc[m][2] += w.x * av0.z + w.y * av1.z + w.z * av2.z + w.w * av3.z;
                acc[m][3] += w.x * av0.w + w.y * av1.w + w.z * av2.w + w.w * av3.w;
            }
        }
        __syncthreads();
    }
#pragma unroll
    for (int m = 0; m < 4; m++)
#pragma unroll
        for (int cc = 0; cc < 4; cc++)
            part[(size_t)((slot * BB + b4 + cc) << 12) + rowbase + rg + (m << 6)] = acc[m][cc];
    __syncthreads();
}

// loc conv+dense for one (b, 64-wide t chunk) of step t+1
__device__ void loc64(int b, int e, const float* __restrict__ lw,
                      const float* __restrict__ ld_, float* sbuf, int tid) {
    float* win = sbuf;           // 2 x 96
    float* locs = sbuf + 192;    // 32 x 64
    int t0 = e * 64;
    if (tid < 192) {
        int ch = tid / 96, idx = tid % 96;
        int tt = t0 - 15 + idx;
        bool ok = (idx < 94) && (tt >= 0) && (tt < TENC);
        const float* src = ch ? g_wcum : g_w;
        win[ch * 96 + idx] = ok ? __ldcg(&src[b * TENC + tt]) : 0.f;
    }
    __syncthreads();
    for (int i = tid; i < 2048; i += NTHR) {
        int c = i >> 6, tt = i & 63;
        float acc = 0.f;
#pragma unroll
        for (int ch = 0; ch < 2; ch++)
#pragma unroll
            for (int kk = 0; kk < 31; kk++)
                acc += win[ch * 96 + tt + kk] * lw[c * 62 + ch * 31 + kk];
        locs[c * 64 + tt] = acc;
    }
    __syncthreads();
    int f = tid & 127, tg = tid >> 7;
    float ldr[32];
#pragma unroll
    for (int c = 0; c < 32; c++) ldr[c] = ld_[f * 32 + c];
    for (int tt = tg * 32; tt < tg * 32 + 32; tt++) {
        float acc = 0.f;
#pragma unroll
        for (int c = 0; c < 32; c++) acc += locs[c * 64 + tt] * ldr[c];
        g_procloc[((size_t)(b * TENC + t0 + tt)) * ADIM + f] = acc;
    }
    __syncthreads();
}

// projection for 16 rows, frame t-1, act-chunked for coalescing
__device__ void proj_unit2(int t, int v, const float* __restrict__ pw,
                           const float* __restrict__ pb, float* __restrict__ out_mel,
                           float* act, int tid) {
    int r = v * 16 + (tid >> 4), b = tid & 15;
    const float* wr = pw + (size_t)r * 1536;
    const float* cx = g_ctx + ((t - 1) & 1) * DENC * BB;
    float acc = 0.f;
    for (int ch = 0; ch < 6; ch++) {
        const float* src = (ch < 4) ? g_hdT + ch * 256 * BB : cx + (ch - 4) * 256 * BB;
        stage(act, src, 256 * BB, tid);
        __syncthreads();
        const float* w = wr + ch * 256;
#pragma unroll 8
        for (int k = 0; k < 256; k += 4) {
            float4 wv = *(const float4*)(w + k);
            acc += wv.x * act[(k + 0) * BB + b] + wv.y * act[(k + 1) * BB + b] +
                   wv.z * act[(k + 2) * BB + b] + wv.w * act[(k + 3) * BB + b];
        }
        __syncthreads();
    }
    acc += pb[r];
    int flat = (t - 1) * FRAME + r;
    out_mel[(size_t)b * (NMEL * 600) + (flat % NMEL) * 600 + flat / NMEL] = acc;
}

__global__ void __launch_bounds__(NTHR) k_mega(
    const float* __restrict__ memory, const int* __restrict__ mlen,
    const float* __restrict__ aw_ih, const float* __restrict__ aw_hh,
    const float* __restrict__ ab_ih, const float* __restrict__ ab_hh,
    const float* __restrict__ dw_ih, const float* __restrict__ dw_hh,
    const float* __restrict__ db_ih, const float* __restrict__ db_hh,
    const float* __restrict__ Wq, const float* __restrict__ v_att,
    const float* __restrict__ lconv, const float* __restrict__ ldense,
    const float* __restrict__ proj_w, const float* __restrict__ proj_b,
    float* __restrict__ out_mel, float* __restrict__ out_align)
{
    extern __shared__ float dsm[];
    float* act = dsm;                 // [4096]
    float* wbufs = dsm + 4096;        // [2][256*WB_STRIDE]
    float* sh = dsm;                  // Phase A alias
    __shared__ int sh_u;
    int cta = blockIdx.x, tid = threadIdx.x;
    unsigned ph = 0;

    for (int t = 0; t <= TSTEPS; t++) {
        // =========== Phase A ===========
        if (cta < 16 && t < TSTEPS) {
            int b = cta;
            float* s_ha = sh;
            for (int j = tid; j < ARNN; j += NTHR) {
                float g[4];
#pragma unroll
                for (int gi = 0; gi < 4; gi++) {
                    int row = gi * 1024 + j;
                    float s = ab_ih[row] + ab_hh[row];
#pragma unroll
                    for (int sl = 0; sl < 8; sl++)
                        s += __ldcg(&g_pA[(size_t)((sl * BB + b) << 12) + row]);
                    g[gi] = s;
                }
                float c = sigf(g[1]) * __ldcg(&g_caT[j * BB + b]) + sigf(g[0]) * tanhf(g[2]);
                float h = sigf(g[3]) * tanhf(c);
                g_caT[j * BB + b] = c;
                g_haT[j * BB + b] = h;
                s_ha[j] = h;
            }
            __syncthreads();
            {
                int f = tid & 127, hf = tid >> 7;
                const float* wr = Wq + (size_t)f * ARNN + hf * 512;
                const float* ha = s_ha + hf * 512;
                float acc = 0.f;
#pragma unroll 4
                for (int k = 0; k < 512; k += 4) {
                    float4 wv = *(const float4*)(wr + k);
                    acc += wv.x * ha[k] + wv.y * ha[k + 1] + wv.z * ha[k + 2] + wv.w * ha[k + 3];
                }
                sh[1024 + tid] = acc;
            }
            __syncthreads();
            if (tid < 128) {
                sh[1280 + tid] = sh[1024 + tid] + sh[1152 + tid];
                sh[1408 + tid] = v_att[tid];
            }
            __syncthreads();
            int L = mlen[b];
            float ev[2];
#pragma unroll
            for (int it = 0; it < 2; it++) {
                int tt = tid + it * 256;
                const float* pl = &g_procloc[((size_t)b * TENC + tt) * ADIM];
                const float* pv = &g_pm[((size_t)b * TENC + tt) * ADIM];
                float acc = 0.f;
#pragma unroll 4
                for (int f = 0; f < ADIM; f += 4) {
                    float4 a = __ldcg((const float4*)(pl + f));
                    float4 p = *(const float4*)(pv + f);
                    acc += sh[1408 + f + 0] * tanh_fast(sh[1280 + f + 0] + a.x + p.x);
                    acc += sh[1408 + f + 1] * tanh_fast(sh[1280 + f + 1] + a.y + p.y);
                    acc += sh[1408 + f + 2] * tanh_fast(sh[1280 + f + 2] + a.z + p.z);
                    acc += sh[1408 + f + 3] * tanh_fast(sh[1280 + f + 3] + a.w + p.w);
                }
                ev[it] = (tt >= L) ? -1e9f : acc;
            }
            float* red = sh + 1536;
            red[tid] = fmaxf(ev[0], ev[1]);
            __syncthreads();
            for (int s = 128; s > 0; s >>= 1) {
                if (tid < s) red[tid] = fmaxf(red[tid], red[tid + s]);
                __syncthreads();
            }
            float mx = red[0];
            __syncthreads();
            float ex0 = expf(ev[0] - mx), ex1 = expf(ev[1] - mx);
            red[tid] = ex0 + ex1;
            __syncthreads();
            for (int s = 128; s > 0; s >>= 1) {
                if (tid < s) red[tid] += red[tid + s];
                __syncthreads();
            }
            float inv = 1.f / red[0];
            {
                float wv = ex0 * inv;
                g_w[b * TENC + tid] = wv;
                g_wcum[b * TENC + tid] = __ldcg(&g_wcum[b * TENC + tid]) + wv;
                out_align[((size_t)b * TSTEPS + t) * TENC + tid] = wv;
                wv = ex1 * inv;
                g_w[b * TENC + tid + 256] = wv;
                g_wcum[b * TENC + tid + 256] = __ldcg(&g_wcum[b * TENC + tid + 256]) + wv;
                out_align[((size_t)b * TSTEPS + t) * TENC + tid + 256] = wv;
            }
            __syncthreads();
            __threadfence();
            if (tid == 0) *(volatile int*)&g_wflag[b * 32] = t + 1;
        } else if (cta >= 16 && cta < 80 && t < TSTEPS) {
            int v = cta - 16, b = v >> 2, d0 = (v & 3) * 128;
            if (tid == 0) {
                while (*(volatile int*)&g_wflag[b * 32] != t + 1) __nanosleep(32);
            }
            __syncthreads();
            for (int i = tid; i < TENC; i += NTHR) sh[i] = __ldcg(&g_w[b * TENC + i]);
            __syncthreads();
            int dd = tid & 127, hf = tid >> 7;
            const float* mb = memory + ((size_t)b * TENC + hf * 256) * DENC + d0 + dd;
            float acc = 0.f;
#pragma unroll 8
            for (int tt = 0; tt < 256; tt++)
                acc += sh[hf * 256 + tt] * mb[(size_t)tt * DENC];
            sh[512 + tid] = acc;
            __syncthreads();
            if (tid < 128)
                g_ctx[(t & 1) * DENC * BB + (d0 + tid) * BB + b] = sh[512 + tid] + sh[640 + tid];
        } else if (cta >= 80 && cta < 144 && t > 0) {
            int v = cta - 80, b = v >> 2, j = (v & 3) * 256 + tid;
            float g[4];
#pragma unroll
            for (int gi = 0; gi < 4; gi++) {
                int row = gi * 1024 + j;
                float s = db_ih[row] + db_hh[row];
#pragma unroll
                for (int sl = 0; sl < 10; sl++)
                    s += __ldcg(&g_pD[(size_t)((sl * BB + b) << 12) + row]);
                g[gi] = s;
            }
            float c = sigf(g[1]) * __ldcg(&g_cdT[j * BB + b]) + sigf(g[0]) * tanhf(g[2]);
            float h = sigf(g[3]) * tanhf(c);
            g_cdT[j * BB + b] = c;
            g_hdT[j * BB + b] = h;
        }
        gsync(++ph);
        if (t == TSTEPS) break;

        // =========== Phase B: dynamic work queue ===========
        const float* ctx_t = g_ctx + (t & 1) * DENC * BB;
        for (;;) {
            if (tid == 0) sh_u = (int)atomicAdd(&g_qcnt[t], 1u);
            __syncthreads();
            int u = sh_u;
            __syncthreads();
            if (u >= NUNITS) break;
            if (u < 160) {
                int rc = u / 10, kc = u % 10;
                gate_unit2(act, wbufs,
                           dw_ih, 1536, 1536, dw_hh, 1024,
                           g_haT, 1024, ctx_t, 512, g_hdT, 1024,
                           g_pD, kc, rc * 256, kc * 256, 256, tid);
            } else if (u < 288) {
                if (t < TSTEPS - 1) {
                    int v = u - 160, rc = v >> 3, kc = v & 7;
                    gate_unit2(act, wbufs,
                               aw_ih, 768, 768, aw_hh, 1024,
                               g_preT + (size_t)(t + 1) * PRE * BB, 256, ctx_t, 512, g_haT, 1024,
                               g_pA, kc, rc * 256, kc * 224, 224, tid);
                }
            } else if (u < 416) {
                if (t < TSTEPS - 1) {
                    int v = u - 288;
                    loc64(v >> 3, v & 7, lconv, ldense, act, tid);
                }
            } else {
                if (t > 0) proj_unit2(t, u - 416, proj_w, proj_b, out_mel, act, tid);
            }
        }
        gsync(++ph);
    }

    // epilogue: final frame t=199
    if (cta < 15) proj_unit2(TSTEPS, cta, proj_w, proj_b, out_mel, act, tid);
}

extern "C" void kernel_launch(void* const* d_in, const int* in_sizes, int n_in,
                              void* d_out, int out_size) {
    const float* memory = (const float*)d_in[0];
    const float* dec_in = (const float*)d_in[1];
    const int*   mlen   = (const int*)d_in[2];
    const float* pw1    = (const float*)d_in[3];
    const float* pw2    = (const float*)d_in[4];
    const float* aw_ih  = (const float*)d_in[5];
    const float* aw_hh  = (const float*)d_in[6];
    const float* ab_ih  = (const float*)d_in[7];
    const float* ab_hh  = (const float*)d_in[8];
    const float* dw_ih  = (const float*)d_in[9];
    const float* dw_hh  = (const float*)d_in[10];
    const float* db_ih  = (const float*)d_in[11];
    const float* db_hh  = (const float*)d_in[12];
    const float* Wq     = (const float*)d_in[13];
    const float* Wm     = (const float*)d_in[14];
    const float* v_att  = (const float*)d_in[15];
    const float* lconv  = (const float*)d_in[16];
    const float* ldense = (const float*)d_in[17];
    const float* proj_w = (const float*)d_in[18];
    const float* proj_b = (const float*)d_in[19];

    float* out = (float*)d_out;
    float* align_out = out + (size_t)BB * NMEL * 600;

    float *s_xraw, *s_h1, *s_preT, *s_pm;
    cudaGetSymbolAddress((void**)&s_xraw, g_xraw);
    cudaGetSymbolAddress((void**)&s_h1, g_h1);
    cudaGetSymbolAddress((void**)&s_preT, g_preT);
    cudaGetSymbolAddress((void**)&s_pm, g_pm);

    static int smem_set = 0;
    int smem_bytes = SMEM_FLOATS * 4;
    if (!smem_set) {
        cudaFuncSetAttribute(k_mega, cudaFuncAttributeMaxDynamicSharedMemorySize, smem_bytes);
        smem_set = 1;
    }

    k_init<<<256, 256>>>();
    k_gather<<<(NFRAMES * BB * FRAME + 255) / 256, 256>>>(dec_in);
    k_sgemm<<<dim3(50, 4), 256>>>(s_xraw, pw1, s_h1, NFRAMES * BB, PRE, FRAME, 1, 0);
    k_sgemm<<<dim3(50, 4), 256>>>(s_h1, pw2, s_preT, NFRAMES * BB, PRE, PRE, 1, 1);
    k_sgemm<<<dim3(128, 2), 256>>>(memory, Wm, s_pm, BB * TENC, ADIM, DENC, 0, 0);

    k_mega<<<GRID, NTHR, smem_bytes>>>(memory, mlen,
                           aw_ih, aw_hh, ab_ih, ab_hh,
                           dw_ih, dw_hh, db_ih, db_hh,
                           Wq, v_att, lconv, ldense, proj_w, proj_b,
                           out, align_out);
}

// round 9
// speedup vs baseline: 1.8944x; 1.3830x over previous
#include <cuda_runtime.h>
#include <cuda_fp16.h>
#include <math.h>

#define BB 16
#define TENC 512
#define DENC 512
#define NMEL 80
#define FRAME 240
#define TSTEPS 200
#define NFRAMES 199
#define PRE 256
#define ARNN 1024
#define ADIM 128
#define GRID 148
#define NTHR 256
#define NUNITS 431
#define WSTH 40                               // half stride per weight row in smem (80B)
#define SMEM_FLOATS (4096 + (2 * 256 * WSTH + 1) / 2)

__device__ float g_xraw[NFRAMES * BB * FRAME];
__device__ float g_h1[NFRAMES * BB * PRE];
__device__ float g_preT[TSTEPS * PRE * BB];     // [t][f][b]
__device__ float g_pm[BB * TENC * ADIM];
__device__ float g_procloc[BB * TENC * ADIM];
__device__ float g_haT[ARNN * BB];              // [j][b]
__device__ float g_caT[ARNN * BB];
__device__ float g_hdT[ARNN * BB];
__device__ float g_cdT[ARNN * BB];
__device__ float g_ctx[2 * DENC * BB];          // [parity][d][b]
__device__ float g_w[BB * TENC];
__device__ float g_wcum[BB * TENC];
__device__ float g_pA[8 * BB * 4096];           // [slot][b][row]
__device__ float g_pD[10 * BB * 4096];
__device__ int   g_wflag[BB * 32];
__device__ unsigned g_qcnt[TSTEPS];
__device__ __align__(128) unsigned g_barA[32];
__device__ __align__(128) unsigned g_barB[32];

// fp16 copies (converted once in prologue)
__device__ __align__(16) __half h_awih[4096 * 768];
__device__ __align__(16) __half h_awhh[4096 * 1024];
__device__ __align__(16) __half h_dwih[4096 * 1536];
__device__ __align__(16) __half h_dwhh[4096 * 1024];
__device__ __align__(16) __half h_mem[BB * TENC * DENC];

__device__ __forceinline__ float sigf(float x) { return 1.f / (1.f + expf(-x)); }
__device__ __forceinline__ float tanh_fast(float x) {
    float y; asm("tanh.approx.f32 %0, %1;" : "=f"(y) : "f"(x)); return y;
}

// cp.async 16B, L2-only (keep L1 for resident read-only slices)
__device__ __forceinline__ void cp16cg(__half* s, const __half* g) {
    unsigned ss = (unsigned)__cvta_generic_to_shared(s);
    asm volatile("cp.async.cg.shared.global [%0], [%1], 16;" :: "r"(ss), "l"(g));
}
__device__ __forceinline__ void cp_commit() { asm volatile("cp.async.commit_group;"); }
__device__ __forceinline__ void cp_wait0() { asm volatile("cp.async.wait_group 0;"); }
__device__ __forceinline__ void cp_wait1() { asm volatile("cp.async.wait_group 1;"); }

__device__ __forceinline__ void gsync(unsigned ph) {
    __threadfence();
    __syncthreads();
    if (threadIdx.x == 0) {
        if (atomicAdd(&g_barA[0], 1u) == GRID - 1) {
            g_barA[0] = 0;
            __threadfence();
            *(volatile unsigned*)&g_barB[0] = ph;
        } else {
            while (*(volatile unsigned*)&g_barB[0] != ph) __nanosleep(32);
            __threadfence();
        }
    }
    __syncthreads();
}

__global__ void k_init() {
    int i = blockIdx.x * 256 + threadIdx.x;
    int st = gridDim.x * 256;
    if (i == 0) { g_barA[0] = 0; g_barB[0] = 0; }
    if (i < TSTEPS) g_qcnt[i] = 0;
    for (int k = i; k < ARNN * BB; k += st) { g_haT[k]=0.f; g_caT[k]=0.f; g_hdT[k]=0.f; g_cdT[k]=0.f; }
    for (int k = i; k < 2 * DENC * BB; k += st) g_ctx[k] = 0.f;
    for (int k = i; k < BB * TENC; k += st) { g_w[k] = 0.f; g_wcum[k] = 0.f; }
    for (int k = i; k < PRE * BB; k += st) g_preT[k] = 0.f;
    for (int k = i; k < BB * 32; k += st) g_wflag[k] = 0;
    for (int k = i; k < 8 * BB * 4096; k += st) g_pA[k] = 0.f;
    for (int k = i; k < BB * TENC * ADIM; k += st) g_procloc[k] = 0.f;
}

__global__ void k_tohalf(const float* __restrict__ s, __half* __restrict__ d, int n) {
    int i = blockIdx.x * 256 + threadIdx.x;
    int st = gridDim.x * 256;
    for (; i < n; i += st) d[i] = __float2half(s[i]);
}

__global__ void k_gather(const float* __restrict__ din) {
    int idx = blockIdx.x * 256 + threadIdx.x;
    if (idx >= NFRAMES * BB * FRAME) return;
    int j = idx % FRAME, m = idx / FRAME;
    int b = m % BB, d = m / BB;
    int flat = d * FRAME + j;
    g_xraw[idx] = din[(b * NMEL + flat % NMEL) * 600 + flat / NMEL];
}

__global__ void k_sgemm(const float* __restrict__ A, const float* __restrict__ Bw,
                        float* __restrict__ C, int M, int N, int K, int relu, int mode) {
    __shared__ float As[16][68];
    __shared__ float Bs[16][68];
    int m0 = blockIdx.x * 64, n0 = blockIdx.y * 64;
    int tx = threadIdx.x, tr = tx >> 4, tc = tx & 15;
    float acc[4][4] = {};
    for (int k0 = 0; k0 < K; k0 += 16) {
        for (int i = tx; i < 1024; i += 256) {
            int mm = i >> 4, kk = i & 15;
            int m = m0 + mm, k = k0 + kk;
            As[kk][mm] = (m < M) ? A[(size_t)m * K + k] : 0.f;
            int n = n0 + mm;
            Bs[kk][mm] = (n < N) ? Bw[(size_t)n * K + k] : 0.f;
        }
        __syncthreads();
#pragma unroll
        for (int kk = 0; kk < 16; kk++) {
            float4 a4 = *(const float4*)&As[kk][tr * 4];
            float4 b4 = *(const float4*)&Bs[kk][tc * 4];
            float a_[4] = {a4.x, a4.y, a4.z, a4.w};
            float b_[4] = {b4.x, b4.y, b4.z, b4.w};
#pragma unroll
            for (int r = 0; r < 4; r++)
#pragma unroll
                for (int c = 0; c < 4; c++) acc[r][c] += a_[r] * b_[c];
        }
        __syncthreads();
    }
    for (int r = 0; r < 4; r++)
        for (int c = 0; c < 4; c++) {
            int m = m0 + tr * 4 + r, n = n0 + tc * 4 + c;
            if (m < M && n < N) {
                float v = acc[r][c];
                if (relu) v = fmaxf(v, 0.f);
                if (mode == 0) C[(size_t)m * N + n] = v;
                else C[(((m >> 4) + 1) * PRE + n) * BB + (m & 15)] = v;
            }
        }
}

__device__ __forceinline__ void stage(float* dst, const float* src, int nfloats, int tid) {
    const float4* s4 = (const float4*)src;
    float4* d4 = (float4*)dst;
    int n4 = nfloats >> 2;
    for (int i = tid; i < n4; i += NTHR) d4[i] = __ldcg(s4 + i);
}

// ---- cp.async-pipelined gate unit (fp16 weights): 256 rows x W k-cols ----
__device__ void gate_unit2(float* act, __half* wbufs,
    const __half* wA, int strA, int lenA, const __half* wB, int strB,
    const float* a0, int l0, const float* a1, int l1, const float* a2, int l2,
    float* part, int slot, int rowbase, int kbeg, int W, int tid)
{
    int kend = kbeg + W;
    {
        int o0s = max(kbeg, 0), o0e = min(kend, l0);
        if (o0e > o0s) stage(act + (o0s - kbeg) * BB, a0 + o0s * BB, (o0e - o0s) * BB, tid);
        int s1s = l0, s1e = l0 + l1;
        int o1s = max(kbeg, s1s), o1e = min(kend, s1e);
        if (l1 && o1e > o1s) stage(act + (o1s - kbeg) * BB, a1 + (o1s - s1s) * BB, (o1e - o1s) * BB, tid);
        int s2s = s1e, s2e = s1e + l2;
        int o2s = max(kbeg, s2s), o2e = min(kend, s2e);
        if (l2 && o2e > o2s) stage(act + (o2s - kbeg) * BB, a2 + (o2s - s2s) * BB, (o2e - o2s) * BB, tid);
    }
    int nch = W >> 5;
    int lrow = tid >> 2, lkh = (tid & 3) * 8;   // 4 threads/row, 16B each, 4 row-sweeps
    {
        int kg = kbeg;
        const __half* ws; int wst; int ko;
        if (kg < lenA) { ws = wA; wst = strA; ko = kg; } else { ws = wB; wst = strB; ko = kg - lenA; }
#pragma unroll
        for (int i = 0; i < 4; i++) {
            int row = lrow + i * 64;
            cp16cg(wbufs + row * WSTH + lkh, ws + (size_t)(rowbase + row) * wst + ko + lkh);
        }
        cp_commit();
    }
    int rg = tid >> 2, b4 = (tid & 3) * 4;
    float acc[4][4] = {};
    for (int c = 0; c < nch; c++) {
        if (c + 1 < nch) {
            int kg = kbeg + (c + 1) * 32;
            const __half* ws; int wst; int ko;
            if (kg < lenA) { ws = wA; wst = strA; ko = kg; } else { ws = wB; wst = strB; ko = kg - lenA; }
            __half* dst = wbufs + ((c + 1) & 1) * (256 * WSTH);
#pragma unroll
            for (int i = 0; i < 4; i++) {
                int row = lrow + i * 64;
                cp16cg(dst + row * WSTH + lkh, ws + (size_t)(rowbase + row) * wst + ko + lkh);
            }
            cp_commit();
            cp_wait1();
        } else {
            cp_wait0();
        }
        __syncthreads();
        const __half* wb = wbufs + (c & 1) * (256 * WSTH);
        const float* ac = act + c * 32 * BB;
#pragma unroll
        for (int l = 0; l < 32; l += 4) {
            float4 av0 = *(const float4*)&ac[(l + 0) * BB + b4];
            float4 av1 = *(const float4*)&ac[(l + 1) * BB + b4];
            float4 av2 = *(const float4*)&ac[(l + 2) * BB + b4];
            float4 av3 = *(const float4*)&ac[(l + 3) * BB + b4];
#pragma unroll
            for (int m = 0; m < 4; m++) {
                uint2 wr = *(const uint2*)(wb + (rg + (m << 6)) * WSTH + l);
                float2 w01 = __half22float2(*reinterpret_cast<__half2*>(&wr.x));
                float2 w23 = __half22float2(*reinterpret_cast<__half2*>(&wr.y));
                acc[m][0] += w01.x * av0.x + w01.y * av1.x + w23.x * av2.x + w23.y * av3.x;
                acc[m][1] += w01.x * av0.y + w01.y * av1.y + w23.x * av2.y + w23.y * av3.y;
                acc[m][2] += w01.x * av0.z + w01.y * av1.z + w23.x * av2.z + w23.y * av3.z;
                acc[m][3] += w01.x * av0.w + w01.y * av1.w + w23.x * av2.w + w23.y * av3.w;
            }
        }
        __syncthreads();
    }
#pragma unroll
    for (int m = 0; m < 4; m++)
#pragma unroll
        for (int cc = 0; cc < 4; cc++)
            part[(size_t)((slot * BB + b4 + cc) << 12) + rowbase + rg + (m << 6)] = acc[m][cc];
    __syncthreads();
}

__device__ void loc64(int b, int e, const float* __restrict__ lw,
                      const float* __restrict__ ld_, float* sbuf, int tid) {
    float* win = sbuf;
    float* locs = sbuf + 192;
    int t0 = e * 64;
    if (tid < 192) {
        int ch = tid / 96, idx = tid % 96;
        int tt = t0 - 15 + idx;
        bool ok = (idx < 94) && (tt >= 0) && (tt < TENC);
        const float* src = ch ? g_wcum : g_w;
        win[ch * 96 + idx] = ok ? __ldcg(&src[b * TENC + tt]) : 0.f;
    }
    __syncthreads();
    for (int i = tid; i < 2048; i += NTHR) {
        int c = i >> 6, tt = i & 63;
        float acc = 0.f;
#pragma unroll
        for (int ch = 0; ch < 2; ch++)
#pragma unroll
            for (int kk = 0; kk < 31; kk++)
                acc += win[ch * 96 + tt + kk] * lw[c * 62 + ch * 31 + kk];
        locs[c * 64 + tt] = acc;
    }
    __syncthreads();
    int f = tid & 127, tg = tid >> 7;
    float ldr[32];
#pragma unroll
    for (int c = 0; c < 32; c++) ldr[c] = ld_[f * 32 + c];
    for (int tt = tg * 32; tt < tg * 32 + 32; tt++) {
        float acc = 0.f;
#pragma unroll
        for (int c = 0; c < 32; c++) acc += locs[c * 64 + tt] * ldr[c];
        g_procloc[((size_t)(b * TENC + t0 + tt)) * ADIM + f] = acc;
    }
    __syncthreads();
}

__device__ void proj_unit2(int t, int v, const float* __restrict__ pw,
                           const float* __restrict__ pb, float* __restrict__ out_mel,
                           float* act, int tid) {
    int r = v * 16 + (tid >> 4), b = tid & 15;
    const float* wr = pw + (size_t)r * 1536;
    const float* cx = g_ctx + ((t - 1) & 1) * DENC * BB;
    float acc = 0.f;
    for (int ch = 0; ch < 6; ch++) {
        const float* src = (ch < 4) ? g_hdT + ch * 256 * BB : cx + (ch - 4) * 256 * BB;
        stage(act, src, 256 * BB, tid);
        __syncthreads();
        const float* w = wr + ch * 256;
#pragma unroll 8
        for (int k = 0; k < 256; k += 4) {
            float4 wv = *(const float4*)(w + k);
            acc += wv.x * act[(k + 0) * BB + b] + wv.y * act[(k + 1) * BB + b] +
                   wv.z * act[(k + 2) * BB + b] + wv.w * act[(k + 3) * BB + b];
        }
        __syncthreads();
    }
    acc += pb[r];
    int flat = (t - 1) * FRAME + r;
    out_mel[(size_t)b * (NMEL * 600) + (flat % NMEL) * 600 + flat / NMEL] = acc;
}

__global__ void __launch_bounds__(NTHR) k_mega(
    const int* __restrict__ mlen,
    const float* __restrict__ ab_ih, const float* __restrict__ ab_hh,
    const float* __restrict__ db_ih, const float* __restrict__ db_hh,
    const float* __restrict__ Wq, const float* __restrict__ v_att,
    const float* __restrict__ lconv, const float* __restrict__ ldense,
    const float* __restrict__ proj_w, const float* __restrict__ proj_b,
    float* __restrict__ out_mel, float* __restrict__ out_align)
{
    extern __shared__ float dsm[];
    float* act = dsm;                               // [4096]
    __half* wbufs = (__half*)(dsm + 4096);          // [2][256*WSTH]
    float* sh = dsm;                                // Phase A alias
    __shared__ int sh_u;
    int cta = blockIdx.x, tid = threadIdx.x;
    unsigned ph = 0;

    for (int t = 0; t <= TSTEPS; t++) {
        // =========== Phase A ===========
        if (cta < 16 && t < TSTEPS) {
            int b = cta;
            float* s_ha = sh;
            for (int j = tid; j < ARNN; j += NTHR) {
                float g[4];
#pragma unroll
                for (int gi = 0; gi < 4; gi++) {
                    int row = gi * 1024 + j;
                    float s = ab_ih[row] + ab_hh[row];
#pragma unroll
                    for (int sl = 0; sl < 8; sl++)
                        s += __ldcg(&g_pA[(size_t)((sl * BB + b) << 12) + row]);
                    g[gi] = s;
                }
                float c = sigf(g[1]) * __ldcg(&g_caT[j * BB + b]) + sigf(g[0]) * tanhf(g[2]);
                float h = sigf(g[3]) * tanhf(c);
                g_caT[j * BB + b] = c;
                g_haT[j * BB + b] = h;
                s_ha[j] = h;
            }
            __syncthreads();
            {
                int f = tid & 127, hf = tid >> 7;
                const float* wr = Wq + (size_t)f * ARNN + hf * 512;
                const float* ha = s_ha + hf * 512;
                float acc = 0.f;
#pragma unroll 4
                for (int k = 0; k < 512; k += 4) {
                    float4 wv = *(const float4*)(wr + k);
                    acc += wv.x * ha[k] + wv.y * ha[k + 1] + wv.z * ha[k + 2] + wv.w * ha[k + 3];
                }
                sh[1024 + tid] = acc;
            }
            __syncthreads();
            if (tid < 128) {
                sh[1280 + tid] = sh[1024 + tid] + sh[1152 + tid];
                sh[1408 + tid] = v_att[tid];
            }
            __syncthreads();
            int L = mlen[b];
            float ev[2];
#pragma unroll
            for (int it = 0; it < 2; it++) {
                int tt = tid + it * 256;
                const float* pl = &g_procloc[((size_t)b * TENC + tt) * ADIM];
                const float* pv = &g_pm[((size_t)b * TENC + tt) * ADIM];
                float acc = 0.f;
#pragma unroll 4
                for (int f = 0; f < ADIM; f += 4) {
                    float4 a = __ldcg((const float4*)(pl + f));
                    float4 p = __ldg((const float4*)(pv + f));
                    acc += sh[1408 + f + 0] * tanh_fast(sh[1280 + f + 0] + a.x + p.x);
                    acc += sh[1408 + f + 1] * tanh_fast(sh[1280 + f + 1] + a.y + p.y);
                    acc += sh[1408 + f + 2] * tanh_fast(sh[1280 + f + 2] + a.z + p.z);
                    acc += sh[1408 + f + 3] * tanh_fast(sh[1280 + f + 3] + a.w + p.w);
                }
                ev[it] = (tt >= L) ? -1e9f : acc;
            }
            float* red = sh + 1536;
            red[tid] = fmaxf(ev[0], ev[1]);
            __syncthreads();
            for (int s = 128; s > 0; s >>= 1) {
                if (tid < s) red[tid] = fmaxf(red[tid], red[tid + s]);
                __syncthreads();
            }
            float mx = red[0];
            __syncthreads();
            float ex0 = expf(ev[0] - mx), ex1 = expf(ev[1] - mx);
            red[tid] = ex0 + ex1;
            __syncthreads();
            for (int s = 128; s > 0; s >>= 1) {
                if (tid < s) red[tid] += red[tid + s];
                __syncthreads();
            }
            float inv = 1.f / red[0];
            {
                float wv = ex0 * inv;
                g_w[b * TENC + tid] = wv;
                g_wcum[b * TENC + tid] = __ldcg(&g_wcum[b * TENC + tid]) + wv;
                out_align[((size_t)b * TSTEPS + t) * TENC + tid] = wv;
                wv = ex1 * inv;
                g_w[b * TENC + tid + 256] = wv;
                g_wcum[b * TENC + tid + 256] = __ldcg(&g_wcum[b * TENC + tid + 256]) + wv;
                out_align[((size_t)b * TSTEPS + t) * TENC + tid + 256] = wv;
            }
            __syncthreads();
            __threadfence();
            if (tid == 0) *(volatile int*)&g_wflag[b * 32] = t + 1;
        } else if (cta >= 16 && cta < 80 && t < TSTEPS) {
            // ctx helpers: fp16 memory, 2 d's per thread, 4-way t split
            int v = cta - 16, b = v >> 2, d0 = (v & 3) * 128;
            if (tid == 0) {
                while (*(volatile int*)&g_wflag[b * 32] != t + 1) __nanosleep(32);
            }
            __syncthreads();
            for (int i = tid; i < TENC; i += NTHR) sh[i] = __ldcg(&g_w[b * TENC + i]);
            __syncthreads();
            int dp = (tid & 63) * 2, hf = tid >> 6;
            const __half* mb = h_mem + ((size_t)b * TENC + hf * 128) * DENC + d0 + dp;
            float a0 = 0.f, a1 = 0.f;
#pragma unroll 8
            for (int tt = 0; tt < 128; tt++) {
                float2 f2 = __half22float2(__ldg((const __half2*)&mb[(size_t)tt * DENC]));
                float wv = sh[512 + 0];   // placeholder avoided below
                wv = sh[hf * 128 + tt];
                a0 += wv * f2.x;
                a1 += wv * f2.y;
            }
            sh[512 + hf * 128 + dp] = a0;
            sh[512 + hf * 128 + dp + 1] = a1;
            __syncthreads();
            if (tid < 128) {
                float s = sh[512 + tid] + sh[640 + tid] + sh[768 + tid] + sh[896 + tid];
                g_ctx[(t & 1) * DENC * BB + (d0 + tid) * BB + b] = s;
            }
        } else if (cta >= 80 && cta < 144 && t > 0) {
            int v = cta - 80, b = v >> 2, j = (v & 3) * 256 + tid;
            float g[4];
#pragma unroll
            for (int gi = 0; gi < 4; gi++) {
                int row = gi * 1024 + j;
                float s = db_ih[row] + db_hh[row];
#pragma unroll
                for (int sl = 0; sl < 10; sl++)
                    s += __ldcg(&g_pD[(size_t)((sl * BB + b) << 12) + row]);
                g[gi] = s;
            }
            float c = sigf(g[1]) * __ldcg(&g_cdT[j * BB + b]) + sigf(g[0]) * tanhf(g[2]);
            float h = sigf(g[3]) * tanhf(c);
            g_cdT[j * BB + b] = c;
            g_hdT[j * BB + b] = h;
        }
        gsync(++ph);
        if (t == TSTEPS) break;

        // =========== Phase B: dynamic work queue ===========
        const float* ctx_t = g_ctx + (t & 1) * DENC * BB;
        for (;;) {
            if (tid == 0) sh_u = (int)atomicAdd(&g_qcnt[t], 1u);
            __syncthreads();
            int u = sh_u;
            __syncthreads();
            if (u >= NUNITS) break;
            if (u < 160) {
                int rc = u / 10, kc = u % 10;
                gate_unit2(act, wbufs,
                           h_dwih, 1536, 1536, h_dwhh, 1024,
                           g_haT, 1024, ctx_t, 512, g_hdT, 1024,
                           g_pD, kc, rc * 256, kc * 256, 256, tid);
            } else if (u < 288) {
                if (t < TSTEPS - 1) {
                    int v = u - 160, rc = v >> 3, kc = v & 7;
                    gate_unit2(act, wbufs,
                               h_awih, 768, 768, h_awhh, 1024,
                               g_preT + (size_t)(t + 1) * PRE * BB, 256, ctx_t, 512, g_haT, 1024,
                               g_pA, kc, rc * 256, kc * 224, 224, tid);
                }
            } else if (u < 416) {
                if (t < TSTEPS - 1) {
                    int v = u - 288;
                    loc64(v >> 3, v & 7, lconv, ldense, act, tid);
                }
            } else {
                if (t > 0) proj_unit2(t, u - 416, proj_w, proj_b, out_mel, act, tid);
            }
        }
        gsync(++ph);
    }

    if (cta < 15) proj_unit2(TSTEPS, cta, proj_w, proj_b, out_mel, act, tid);
}

extern "C" void kernel_launch(void* const* d_in, const int* in_sizes, int n_in,
                              void* d_out, int out_size) {
    const float* memory = (const float*)d_in[0];
    const float* dec_in = (const float*)d_in[1];
    const int*   mlen   = (const int*)d_in[2];
    const float* pw1    = (const float*)d_in[3];
    const float* pw2    = (const float*)d_in[4];
    const float* aw_ih  = (const float*)d_in[5];
    const float* aw_hh  = (const float*)d_in[6];
    const float* ab_ih  = (const float*)d_in[7];
    const float* ab_hh  = (const float*)d_in[8];
    const float* dw_ih  = (const float*)d_in[9];
    const float* dw_hh  = (const float*)d_in[10];
    const float* db_ih  = (const float*)d_in[11];
    const float* db_hh  = (const float*)d_in[12];
    const float* Wq     = (const float*)d_in[13];
    const float* Wm     = (const float*)d_in[14];
    const float* v_att  = (const float*)d_in[15];
    const float* lconv  = (const float*)d_in[16];
    const float* ldense = (const float*)d_in[17];
    const float* proj_w = (const float*)d_in[18];
    const float* proj_b = (const float*)d_in[19];

    float* out = (float*)d_out;
    float* align_out = out + (size_t)BB * NMEL * 600;

    float *s_xraw, *s_h1, *s_preT, *s_pm;
    __half *p_awih, *p_awhh, *p_dwih, *p_dwhh, *p_mem;
    cudaGetSymbolAddress((void**)&s_xraw, g_xraw);
    cudaGetSymbolAddress((void**)&s_h1, g_h1);
    cudaGetSymbolAddress((void**)&s_preT, g_preT);
    cudaGetSymbolAddress((void**)&s_pm, g_pm);
    cudaGetSymbolAddress((void**)&p_awih, h_awih);
    cudaGetSymbolAddress((void**)&p_awhh, h_awhh);
    cudaGetSymbolAddress((void**)&p_dwih, h_dwih);
    cudaGetSymbolAddress((void**)&p_dwhh, h_dwhh);
    cudaGetSymbolAddress((void**)&p_mem, h_mem);

    static int smem_set = 0;
    int smem_bytes = SMEM_FLOATS * 4;
    if (!smem_set) {
        cudaFuncSetAttribute(k_mega, cudaFuncAttributeMaxDynamicSharedMemorySize, smem_bytes);
        smem_set = 1;
    }

    k_init<<<256, 256>>>();
    k_gather<<<(NFRAMES * BB * FRAME + 255) / 256, 256>>>(dec_in);
    k_sgemm<<<dim3(50, 4), 256>>>(s_xraw, pw1, s_h1, NFRAMES * BB, PRE, FRAME, 1, 0);
    k_sgemm<<<dim3(50, 4), 256>>>(s_h1, pw2, s_preT, NFRAMES * BB, PRE, PRE, 1, 1);
    k_sgemm<<<dim3(128, 2), 256>>>(memory, Wm, s_pm, BB * TENC, ADIM, DENC, 0, 0);
    k_tohalf<<<2048, 256>>>(aw_ih, p_awih, 4096 * 768);
    k_tohalf<<<2048, 256>>>(aw_hh, p_awhh, 4096 * 1024);
    k_tohalf<<<2048, 256>>>(dw_ih, p_dwih, 4096 * 1536);
    k_tohalf<<<2048, 256>>>(dw_hh, p_dwhh, 4096 * 1024);
    k_tohalf<<<2048, 256>>>(memory, p_mem, BB * TENC * DENC);

    k_mega<<<GRID, NTHR, smem_bytes>>>(mlen,
                           ab_ih, ab_hh, db_ih, db_hh,
                           Wq, v_att, lconv, ldense, proj_w, proj_b,
                           out, align_out);
}